// round 3
// baseline (speedup 1.0000x reference)
#include <cuda_runtime.h>

// SimpleQNN full analytic collapse:
//  - product state through the local layers; diagonal gates (rz/crz) dead
//  - CNOT chain = parity observables -> prefix products of per-wire Z expectations
//  - NEW (R2): rotation composition collapses the per-wire expectation to
//        z_j[b] = cos(rx_j) * sin(x[b,j] - ry_j)
//    (RY(ry)·H·RY(x)|0> = (cos psi, -sin psi), psi = x/2 - pi/4 - ry/2,
//     a0^2 - a1^2 = cos 2psi = sin(x - ry); RX contributes factor cos(rx))
//  - q[b,w] = prod_{0..w} z (w>=1), q[b,0] = prod_{1..15} z; out = q@W^T + bias
//
// Layout: grid=32 CTAs x 32 threads. One warp = 2 batches (16 lanes each).
// Warp-synchronous width-16 shuffle scans; W/bias prefetched to overlap scan
// latency. No smem, no barriers.

#define NW 16
#define NOUT 10
#define BATCH 64
#define FULL 0xffffffffu

__global__ void __launch_bounds__(32)
qnn_analytic_kernel(const float* __restrict__ x,     // [64,16]
                    const float* __restrict__ ryp,   // [16]
                    const float* __restrict__ rxp,   // [16]
                    const float* __restrict__ W,     // [10,16]
                    const float* __restrict__ bias,  // [10]
                    float* __restrict__ out)         // [64,10]
{
    const int lane = threadIdx.x;            // 0..31
    const int j    = lane & 15;              // wire
    const int b    = (blockIdx.x << 1) | (lane >> 4);   // batch

    // ---- per-(b,j) Z expectation: one sub, two MUFU, one mul
    float z = __cosf(rxp[j]) * __sinf(x[b * NW + j] - ryp[j]);

    // ---- prefetch linear head operands (overlaps with the scans below)
    float wrow[NW];
    float bv = 0.0f;
    if (j < NOUT) {
        bv = bias[j];
#pragma unroll
        for (int w = 0; w < NW; ++w) wrow[w] = W[j * NW + w];
    }

    // ---- inclusive multiply-scan (width 16): p_j = z0*...*zj
    float p = z;
    // ---- parallel second scan with z0 masked: s_15 = prod_{1..15} = q[0]
    float s = (j == 0) ? 1.0f : z;
#pragma unroll
    for (int d = 1; d < 16; d <<= 1) {
        float tp = __shfl_up_sync(FULL, p, d, 16);
        float ts = __shfl_up_sync(FULL, s, d, 16);
        if (j >= d) { p *= tp; s *= ts; }
    }
    float q0 = __shfl_sync(FULL, s, 15, 16);
    float q  = (j == 0) ? q0 : p;            // q[b, j]

    // ---- gather q vector (independent shuffles, pipelined)
    float qv[NW];
#pragma unroll
    for (int w = 0; w < NW; ++w)
        qv[w] = __shfl_sync(FULL, q, w, 16);

    // ---- linear head: lanes 0..9 produce one output each
    if (j < NOUT) {
        float acc = bv;
#pragma unroll
        for (int w = 0; w < NW; ++w)
            acc = fmaf(qv[w], wrow[w], acc);
        out[b * NOUT + j] = acc;
    }
}

extern "C" void kernel_launch(void* const* d_in, const int* in_sizes, int n_in,
                              void* d_out, int out_size)
{
    // metadata order: x, ry_params, rx_params, rz_params, crz_params, W, b
    const float* x    = (const float*)d_in[0];
    const float* ryp  = (const float*)d_in[1];
    const float* rxp  = (const float*)d_in[2];
    // d_in[3] (rz) / d_in[4] (crz): diagonal gates, provably no effect on probs
    const float* W    = (const float*)d_in[5];
    const float* bias = (const float*)d_in[6];
    float* out = (float*)d_out;

    qnn_analytic_kernel<<<BATCH / 2, 32>>>(x, ryp, rxp, W, bias, out);
}

// round 4
// speedup vs baseline: 1.8714x; 1.8714x over previous
#include <cuda_runtime.h>

// SimpleQNN full analytic collapse:
//   z_j[b] = cos(rx_j) * sin(x[b,j] - ry_j)      (RY/H/RY/RX composition)
//   rz/crz diagonal -> dead; CNOT chain -> parity observables:
//   q[b,w] = prod_{0..w} z (w>=1), q[b,0] = prod_{1..15} z
//   out = q @ W^T + bias
//
// R3 layout: ONE CTA, 64 threads, one thread per batch element. No shuffles,
// no smem, no barriers. Per-thread: 4x float4 coalesced load of its x row,
// 32 independent MUFU trig ops, short multiply chains, 10 independent dots.
// Single-CTA keeps the timed-loop (graph replay) behavior on the fast path —
// the 32-CTA spray in R2 regressed wallclock despite a faster isolated kernel.

#define NW 16
#define NOUT 10
#define BATCH 64

__global__ void __launch_bounds__(BATCH)
qnn_analytic_kernel(const float* __restrict__ x,     // [64,16]
                    const float* __restrict__ ryp,   // [16]
                    const float* __restrict__ rxp,   // [16]
                    const float* __restrict__ W,     // [10,16]
                    const float* __restrict__ bias,  // [10]
                    float* __restrict__ out)         // [64,10]
{
    const int b = threadIdx.x;

    // ---- coalesced vector load of this batch's x row (64 bytes)
    const float4* xrow = (const float4*)(x + b * NW);
    float4 x0 = xrow[0], x1 = xrow[1], x2 = xrow[2], x3 = xrow[3];
    float xv[NW] = { x0.x, x0.y, x0.z, x0.w,  x1.x, x1.y, x1.z, x1.w,
                     x2.x, x2.y, x2.z, x2.w,  x3.x, x3.y, x3.z, x3.w };

    // ---- per-wire Z expectations: all 32 MUFU ops independent
    float z[NW];
#pragma unroll
    for (int j = 0; j < NW; ++j)
        z[j] = __cosf(rxp[j]) * __sinf(xv[j] - ryp[j]);

    // ---- prefix products q[w] = z0*...*zw (w>=1); suffix for q[0]
    float q[NW];
    float pref = z[0];
#pragma unroll
    for (int w = 1; w < NW; ++w) { pref *= z[w]; q[w] = pref; }
    float suf = z[1];
#pragma unroll
    for (int j = 2; j < NW; ++j) suf *= z[j];
    q[0] = suf;
    q[1] = z[0] * z[1];

    // ---- linear head: 10 independent 16-FMA dot products
#pragma unroll
    for (int k = 0; k < NOUT; ++k) {
        float acc = bias[k];
#pragma unroll
        for (int w = 0; w < NW; ++w)
            acc = fmaf(q[w], W[k * NW + w], acc);
        out[b * NOUT + k] = acc;
    }
}

extern "C" void kernel_launch(void* const* d_in, const int* in_sizes, int n_in,
                              void* d_out, int out_size)
{
    // metadata order: x, ry_params, rx_params, rz_params, crz_params, W, b
    const float* x    = (const float*)d_in[0];
    const float* ryp  = (const float*)d_in[1];
    const float* rxp  = (const float*)d_in[2];
    // d_in[3] (rz) / d_in[4] (crz): diagonal gates, provably no effect on probs
    const float* W    = (const float*)d_in[5];
    const float* bias = (const float*)d_in[6];
    float* out = (float*)d_out;

    qnn_analytic_kernel<<<1, BATCH>>>(x, ryp, rxp, W, bias, out);
}

// round 6
// speedup vs baseline: 2.4372x; 1.3023x over previous
#include <cuda_runtime.h>

// SimpleQNN full analytic collapse:
//   z_j[b] = cos(rx_j) * sin(x[b,j] - ry_j)   (RY·H·RY·RX composition)
//   rz/crz diagonal -> dead; CNOT chain -> parity observables:
//   q[b,w] = prod_{0..w} z (w>=1), q[b,0] = prod_{1..15} z
//   out = q @ W^T + bias
//
// R4 layout: ONE CTA x 1024 threads (32 warps on one SM -> 8 warps/SMSP for
// latency hiding; single-CTA keeps graph-replay wallclock on the fast path).
// One (batch, wire) pair per thread: 1 coalesced load, 2 MUFU ops, merged
// dual width-16 shuffle scan, gather, 16-FMA dot. Shortest per-warp stream
// of any round so far.

#define NW 16
#define NOUT 10
#define BATCH 64
#define FULL 0xffffffffu

__global__ void __launch_bounds__(BATCH * NW)
qnn_analytic_kernel(const float* __restrict__ x,     // [64,16]
                    const float* __restrict__ ryp,   // [16]
                    const float* __restrict__ rxp,   // [16]
                    const float* __restrict__ W,     // [10,16]
                    const float* __restrict__ bias,  // [16? -> 10]
                    float* __restrict__ out)         // [64,10]
{
    const int tid = threadIdx.x;     // 0..1023, == b*16 + j
    const int j   = tid & 15;        // wire
    const int b   = tid >> 4;        // batch

    // ---- per-(b,j) Z expectation: x load is perfectly coalesced (x[tid])
    float z = __cosf(rxp[j]) * __sinf(x[tid] - ryp[j]);

    // ---- prefetch linear-head operands so their latency overlaps the scans
    float wrow[NW];
    float bv = 0.0f;
    if (j < NOUT) {
        bv = bias[j];
#pragma unroll
        for (int w = 0; w < NW; ++w) wrow[w] = W[j * NW + w];
    }

    // ---- merged dual multiply-scan (width 16):
    //      p: inclusive prefix of z          -> q[w] for w>=1
    //      s: prefix with z0 masked to 1     -> lane15 = prod_{1..15} = q[0]
    float p = z;
    float s = (j == 0) ? 1.0f : z;
#pragma unroll
    for (int d = 1; d < 16; d <<= 1) {
        float tp = __shfl_up_sync(FULL, p, d, 16);
        float ts = __shfl_up_sync(FULL, s, d, 16);
        if (j >= d) { p *= tp; s *= ts; }
    }
    float q0 = __shfl_sync(FULL, s, 15, 16);
    float q  = (j == 0) ? q0 : p;    // q[b, j]

    // ---- gather the group's q vector (16 independent shuffles)
    float qv[NW];
#pragma unroll
    for (int w = 0; w < NW; ++w)
        qv[w] = __shfl_sync(FULL, q, w, 16);

    // ---- linear head: lanes 0..9 each produce one output
    if (j < NOUT) {
        float acc = bv;
#pragma unroll
        for (int w = 0; w < NW; ++w)
            acc = fmaf(qv[w], wrow[w], acc);
        out[b * NOUT + j] = acc;
    }
}

extern "C" void kernel_launch(void* const* d_in, const int* in_sizes, int n_in,
                              void* d_out, int out_size)
{
    // metadata order: x, ry_params, rx_params, rz_params, crz_params, W, b
    const float* x    = (const float*)d_in[0];
    const float* ryp  = (const float*)d_in[1];
    const float* rxp  = (const float*)d_in[2];
    // d_in[3] (rz) / d_in[4] (crz): diagonal gates, provably no effect on probs
    const float* W    = (const float*)d_in[5];
    const float* bias = (const float*)d_in[6];
    float* out = (float*)d_out;

    qnn_analytic_kernel<<<1, BATCH * NW>>>(x, ryp, rxp, W, bias, out);
}

// round 7
// speedup vs baseline: 2.5192x; 1.0337x over previous
#include <cuda_runtime.h>

// SimpleQNN full analytic collapse:
//   z_j[b] = cos(rx_j) * sin(x[b,j] - ry_j)   (RY·H·RY·RX composition)
//   rz/crz diagonal -> dead; CNOT chain -> parity observables:
//   q[b,w] = prod_{0..w} z (w>=1), q[b,0] = prod_{1..15} z
//   out = q @ W^T + bias
//
// R6 layout: grid=2 x 512 threads — one (batch, wire) pair per thread,
// 16 warps on each of 2 SMs. Halves per-SM issue pressure and block ramp
// vs the single-1024-thread CTA (which plateaued at ~5.9us), while staying
// far below the 32-CTA spray that regressed wallclock in R2.
// Dot product split into 4 accumulators to cut the FMA dependency chain.

#define NW 16
#define NOUT 10
#define BATCH 64
#define FULL 0xffffffffu

__global__ void __launch_bounds__(512)
qnn_analytic_kernel(const float* __restrict__ x,     // [64,16]
                    const float* __restrict__ ryp,   // [16]
                    const float* __restrict__ rxp,   // [16]
                    const float* __restrict__ W,     // [10,16]
                    const float* __restrict__ bias,  // [10]
                    float* __restrict__ out)         // [64,10]
{
    const int gid = (blockIdx.x << 9) | threadIdx.x;  // 0..1023 == b*16 + j
    const int j   = gid & 15;         // wire
    const int b   = gid >> 4;         // batch

    // ---- per-(b,j) Z expectation: x load perfectly coalesced (x[gid])
    float z = __cosf(rxp[j]) * __sinf(x[gid] - ryp[j]);

    // ---- prefetch linear-head operands (overlap their latency with scans)
    float wrow[NW];
    float bv = 0.0f;
    if (j < NOUT) {
        bv = bias[j];
#pragma unroll
        for (int w = 0; w < NW; ++w) wrow[w] = W[j * NW + w];
    }

    // ---- merged dual multiply-scan (width 16):
    //      p: inclusive prefix of z       -> q[w] for w>=1
    //      s: prefix with z0 masked to 1  -> lane15 = prod_{1..15} = q[0]
    float p = z;
    float s = (j == 0) ? 1.0f : z;
#pragma unroll
    for (int d = 1; d < 16; d <<= 1) {
        float tp = __shfl_up_sync(FULL, p, d, 16);
        float ts = __shfl_up_sync(FULL, s, d, 16);
        if (j >= d) { p *= tp; s *= ts; }
    }
    float q0 = __shfl_sync(FULL, s, 15, 16);
    float q  = (j == 0) ? q0 : p;     // q[b, j]

    // ---- gather the group's q vector (16 independent shuffles)
    float qv[NW];
#pragma unroll
    for (int w = 0; w < NW; ++w)
        qv[w] = __shfl_sync(FULL, q, w, 16);

    // ---- linear head: lanes 0..9 each produce one output.
    //      4 independent accumulators -> FMA chain 64 -> ~24 cycles.
    if (j < NOUT) {
        float a0 = bv, a1 = 0.0f, a2 = 0.0f, a3 = 0.0f;
#pragma unroll
        for (int w = 0; w < NW; w += 4) {
            a0 = fmaf(qv[w + 0], wrow[w + 0], a0);
            a1 = fmaf(qv[w + 1], wrow[w + 1], a1);
            a2 = fmaf(qv[w + 2], wrow[w + 2], a2);
            a3 = fmaf(qv[w + 3], wrow[w + 3], a3);
        }
        out[b * NOUT + j] = (a0 + a1) + (a2 + a3);
    }
}

extern "C" void kernel_launch(void* const* d_in, const int* in_sizes, int n_in,
                              void* d_out, int out_size)
{
    // metadata order: x, ry_params, rx_params, rz_params, crz_params, W, b
    const float* x    = (const float*)d_in[0];
    const float* ryp  = (const float*)d_in[1];
    const float* rxp  = (const float*)d_in[2];
    // d_in[3] (rz) / d_in[4] (crz): diagonal gates, provably no effect on probs
    const float* W    = (const float*)d_in[5];
    const float* bias = (const float*)d_in[6];
    float* out = (float*)d_out;

    qnn_analytic_kernel<<<2, 512>>>(x, ryp, rxp, W, bias, out);
}

// round 8
// speedup vs baseline: 2.5813x; 1.0246x over previous
#include <cuda_runtime.h>

// SimpleQNN full analytic collapse:
//   z_j[b] = cos(rx_j) * sin(x[b,j] - ry_j)   (RY·H·RY·RX composition)
//   rz/crz diagonal -> dead; CNOT chain -> parity observables:
//   q[b,w] = prod_{0..w} z (w>=1), q[b,0] = prod_{1..15} z
//   out = q @ W^T + bias
//
// R7: grid=1 x 1024 (grid>1 costs ~0.7us wallclock; single CTA is the floor).
// All SHFLs (25/warp in R4, MIO-pipe, 26-cyc lat) replaced by one smem
// round-trip: stage1 stores z[b][j] (STS), one barrier, stage2 lanes j<10
// reload their batch row via 4x LDS.128 (broadcast) and redundantly compute
// prefix/suffix products on the 4-cycle FMA pipe. W/bias prefetched as
// float4 before the barrier to overlap stage1.

#define NW 16
#define NOUT 10
#define BATCH 64

__global__ void __launch_bounds__(BATCH * NW)
qnn_analytic_kernel(const float* __restrict__ x,     // [64,16]
                    const float* __restrict__ ryp,   // [16]
                    const float* __restrict__ rxp,   // [16]
                    const float* __restrict__ W,     // [10,16]
                    const float* __restrict__ bias,  // [10]
                    float* __restrict__ out)         // [64,10]
{
    __shared__ float zsm[BATCH][NW];                 // 4 KB, rows 64B-aligned

    const int tid = threadIdx.x;     // 0..1023 == b*16 + j
    const int j   = tid & 15;        // wire (stage1) / output col k (stage2)
    const int b   = tid >> 4;        // batch

    // ---- stage 1: per-(b,j) Z expectation; x load perfectly coalesced
    zsm[b][j] = __cosf(rxp[j]) * __sinf(x[tid] - ryp[j]);

    // ---- prefetch linear-head operands (overlaps stage1 + barrier)
    float4 w0, w1, w2, w3;
    float  bv = 0.0f;
    if (j < NOUT) {
        const float4* Wr = (const float4*)(W + j * NW);
        w0 = Wr[0]; w1 = Wr[1]; w2 = Wr[2]; w3 = Wr[3];
        bv = bias[j];
    }

    __syncthreads();

    // ---- stage 2: lanes j<10 of each 16-lane group produce out[b][j]
    if (j < NOUT) {
        const float4* zr = (const float4*)zsm[b];    // broadcast within group
        float4 za = zr[0], zb = zr[1], zc = zr[2], zd = zr[3];
        float zv[NW] = { za.x, za.y, za.z, za.w,  zb.x, zb.y, zb.z, zb.w,
                         zc.x, zc.y, zc.z, zc.w,  zd.x, zd.y, zd.z, zd.w };

        // prefix products: q[w] = z0*...*zw  (w >= 1)
        float q[NW];
        float pref = zv[0];
#pragma unroll
        for (int w = 1; w < NW; ++w) { pref *= zv[w]; q[w] = pref; }
        // q[0] = prod_{1..15}: two parallel sub-products, then one mul
        float s1 = zv[1];
#pragma unroll
        for (int w = 2; w <= 8; ++w)  s1 *= zv[w];
        float s2 = zv[9];
#pragma unroll
        for (int w = 10; w < NW; ++w) s2 *= zv[w];
        q[0] = s1 * s2;

        // dot with prefetched W row, 2 independent accumulators
        const float wv[NW] = { w0.x, w0.y, w0.z, w0.w,  w1.x, w1.y, w1.z, w1.w,
                               w2.x, w2.y, w2.z, w2.w,  w3.x, w3.y, w3.z, w3.w };
        float a0 = bv, a1 = 0.0f;
#pragma unroll
        for (int w = 0; w < NW; w += 2) {
            a0 = fmaf(q[w],     wv[w],     a0);
            a1 = fmaf(q[w + 1], wv[w + 1], a1);
        }
        out[b * NOUT + j] = a0 + a1;
    }
}

extern "C" void kernel_launch(void* const* d_in, const int* in_sizes, int n_in,
                              void* d_out, int out_size)
{
    // metadata order: x, ry_params, rx_params, rz_params, crz_params, W, b
    const float* x    = (const float*)d_in[0];
    const float* ryp  = (const float*)d_in[1];
    const float* rxp  = (const float*)d_in[2];
    // d_in[3] (rz) / d_in[4] (crz): diagonal gates, provably no effect on probs
    const float* W    = (const float*)d_in[5];
    const float* bias = (const float*)d_in[6];
    float* out = (float*)d_out;

    qnn_analytic_kernel<<<1, BATCH * NW>>>(x, ryp, rxp, W, bias, out);
}